// round 6
// baseline (speedup 1.0000x reference)
#include <cuda_runtime.h>

// B=8, N=1024, D=256, H=512, M=256, O=256, 4H=2048

__device__ float g_xproj[8 * 1024 * 2048];
__device__ float g_h    [8 * 1024 * 512];
__device__ float g_t1   [8 * 1024 * 256];
__device__ float g_t2   [8 * 1024 * 256];
__device__ float g_t3   [8 * 1024 * 256];
__device__ float g_ax   [8 * 1024 * 256];
__device__ float g_av   [8 * 1024 * 256];
__device__ float g_scores[8 * 1024 * 1024];
__device__ float g_sagg [8 * 1024 * 512];
__device__ float g_agg  [8 * 1024 * 256];
__device__ int   g_hasnb[8 * 1024];
__device__ unsigned g_flags[128];

__device__ __forceinline__ unsigned ld_acq(const unsigned* p) {
    unsigned v;
    asm volatile("ld.acquire.gpu.global.u32 %0, [%1];" : "=r"(v) : "l"(p) : "memory");
    return v;
}
__device__ __forceinline__ void st_rel(unsigned* p, unsigned v) {
    asm volatile("st.release.gpu.global.u32 [%0], %1;" :: "l"(p), "r"(v) : "memory");
}
__device__ __forceinline__ unsigned long long pk2(float lo, float hi) {
    unsigned long long r;
    asm("mov.b64 %0, {%1, %2};" : "=l"(r) : "f"(lo), "f"(hi));
    return r;
}
__device__ __forceinline__ void fma2(unsigned long long& d, unsigned long long a, unsigned long long b) {
    asm("fma.rn.f32x2 %0, %1, %2, %0;" : "+l"(d) : "l"(a), "l"(b));
}
__device__ __forceinline__ float unpk_sum(unsigned long long v) {
    float x, y;
    asm("mov.b64 {%0, %1}, %2;" : "=f"(x), "=f"(y) : "l"(v));
    return x + y;
}
__device__ __forceinline__ float sigf(float x) {
    return __fdividef(1.f, 1.f + __expf(-x));
}
__device__ __forceinline__ float tanhfast(float x) {
    return __fdividef(2.f, 1.f + __expf(-2.f * x)) - 1.f;
}

__global__ void reset_kernel() {
    if (threadIdx.x < 128) g_flags[threadIdx.x] = 0u;
}

// ---------- persistent LSTM: 128 CTAs x 256 thr; CTA owns 4 j-cols (16 gate rows) ----------
// k layout per lane: k = 4*lane + 128*i (i=0..3); f32x2 packed math throughout.
__global__ __launch_bounds__(256, 1) void lstm_kernel(const float* __restrict__ Whh)
{
    __shared__ __align__(16) float hs[8 * 512];
    __shared__ float gsum[16][8];

    const int tid  = threadIdx.x;
    const int w    = tid >> 5;
    const int lane = tid & 31;
    const int j0   = blockIdx.x * 4;

    // Weights for 2 owned rows, packed as f32x2 k-pairs: wp[2*i+half]
    unsigned long long wp0[8], wp1[8];
    {
        int lr0 = 2 * w, lr1 = 2 * w + 1;
        int grow0 = (lr0 >> 2) * 512 + j0 + (lr0 & 3);
        int grow1 = (lr1 >> 2) * 512 + j0 + (lr1 & 3);
        #pragma unroll
        for (int i = 0; i < 4; i++) {
            int k = 4 * lane + 128 * i;
            float4 a = *(const float4*)&Whh[(size_t)grow0 * 512 + k];
            float4 b = *(const float4*)&Whh[(size_t)grow1 * 512 + k];
            wp0[2 * i]     = pk2(a.x, a.y);
            wp0[2 * i + 1] = pk2(a.z, a.w);
            wp1[2 * i]     = pk2(b.x, b.y);
            wp1[2 * i + 1] = pk2(b.z, b.w);
        }
    }

    float c_st = 0.f;
    const int ub  = lane >> 2;   // batch for update lanes
    const int ujl = lane & 3;    // local j for update lanes

    for (int t = 0; t < 1024; ++t) {
        // prefetch x-projection gate inputs (independent of h[t-1])
        float xq0 = 0.f, xq1 = 0.f, xq2 = 0.f, xq3 = 0.f;
        if (tid < 32) {
            size_t base = ((size_t)(ub << 10) + t) * 2048 + j0 + ujl;
            xq0 = g_xproj[base];
            xq1 = g_xproj[base + 512];
            xq2 = g_xproj[base + 1024];
            xq3 = g_xproj[base + 1536];
        }

        if (tid < 128) {
            while (ld_acq(&g_flags[tid]) < (unsigned)t) { }
        }
        __syncthreads();

        if (t == 0) {
            #pragma unroll
            for (int q = 0; q < 4; q++)
                *(float4*)&hs[(tid + 256 * q) * 4] = make_float4(0.f, 0.f, 0.f, 0.f);
        } else {
            #pragma unroll
            for (int q = 0; q < 4; q++) {
                int flat = (tid + 256 * q) * 4;
                int b = flat >> 9, k = flat & 511;
                *(float4*)&hs[flat] =
                    *(const float4*)&g_h[((size_t)(b << 10) + (t - 1)) * 512 + k];
            }
        }
        __syncthreads();

        // matvec: 2 rows x 8 batches, f32x2 packed
        unsigned long long acc0[8], acc1[8];
        #pragma unroll
        for (int b = 0; b < 8; b++) { acc0[b] = 0ull; acc1[b] = 0ull; }
        #pragma unroll
        for (int i = 0; i < 4; i++) {
            const int kb = 4 * lane + 128 * i;
            const unsigned long long w00 = wp0[2 * i], w01 = wp0[2 * i + 1];
            const unsigned long long w10 = wp1[2 * i], w11 = wp1[2 * i + 1];
            #pragma unroll
            for (int b = 0; b < 8; b++) {
                ulonglong2 hv = *(const ulonglong2*)&hs[b * 512 + kb];
                fma2(acc0[b], w00, hv.x);
                fma2(acc0[b], w01, hv.y);
                fma2(acc1[b], w10, hv.x);
                fma2(acc1[b], w11, hv.y);
            }
        }

        float a0[8], a1[8];
        #pragma unroll
        for (int b = 0; b < 8; b++) { a0[b] = unpk_sum(acc0[b]); a1[b] = unpk_sum(acc1[b]); }

        // folded butterfly: masks 16,8,4 fold b (8->4->2->1), masks 2,1 finish reduce
        float r0[8], r1[8];
        #pragma unroll
        for (int b = 0; b < 8; b++) {
            r0[b] = __shfl_xor_sync(0xffffffffu, a0[b], 16);
            r1[b] = __shfl_xor_sync(0xffffffffu, a1[b], 16);
        }
        const int h16 = (lane & 16) ? 4 : 0;
        float c0[4], c1[4];
        #pragma unroll
        for (int j = 0; j < 4; j++) {
            c0[j] = a0[h16 + j] + r0[h16 + j];
            c1[j] = a1[h16 + j] + r1[h16 + j];
        }
        float d0[4], d1[4];
        #pragma unroll
        for (int j = 0; j < 4; j++) {
            d0[j] = __shfl_xor_sync(0xffffffffu, c0[j], 8);
            d1[j] = __shfl_xor_sync(0xffffffffu, c1[j], 8);
        }
        const int h8 = (lane & 8) ? 2 : 0;
        float e0[2], e1[2];
        #pragma unroll
        for (int j = 0; j < 2; j++) {
            e0[j] = c0[h8 + j] + d0[h8 + j];
            e1[j] = c1[h8 + j] + d1[h8 + j];
        }
        float q00 = __shfl_xor_sync(0xffffffffu, e0[0], 4);
        float q01 = __shfl_xor_sync(0xffffffffu, e0[1], 4);
        float q10 = __shfl_xor_sync(0xffffffffu, e1[0], 4);
        float q11 = __shfl_xor_sync(0xffffffffu, e1[1], 4);
        float s0 = (lane & 4) ? (e0[1] + q01) : (e0[0] + q00);
        float s1 = (lane & 4) ? (e1[1] + q11) : (e1[0] + q10);
        s0 += __shfl_xor_sync(0xffffffffu, s0, 2);
        s0 += __shfl_xor_sync(0xffffffffu, s0, 1);
        s1 += __shfl_xor_sync(0xffffffffu, s1, 2);
        s1 += __shfl_xor_sync(0xffffffffu, s1, 1);
        const int bidx = (lane >> 2) & 7;
        if ((lane & 3) == 0)      gsum[2 * w][bidx]     = s0;
        else if ((lane & 3) == 1) gsum[2 * w + 1][bidx] = s1;
        __syncthreads();

        if (tid < 32) {
            float gi = gsum[0  + ujl][ub] + xq0;
            float gf = gsum[4  + ujl][ub] + xq1;
            float gg = gsum[8  + ujl][ub] + xq2;
            float go = gsum[12 + ujl][ub] + xq3;
            float si = sigf(gi);
            float sf = sigf(gf);
            float so = sigf(go);
            float tg = tanhfast(gg);
            c_st = sf * c_st + si * tg;
            float hN = so * tanhfast(c_st);
            g_h[((size_t)(ub << 10) + t) * 512 + j0 + ujl] = hN;
            __syncwarp();
            if (lane == 0) st_rel(&g_flags[blockIdx.x], (unsigned)(t + 1));
        }
    }
}

// ---------- generic tiled fp32 GEMM: C = A @ op(B) (+bias[+bias2]) [ReLU] [ACC] [rowmask] ----------
// TB==0: B is [N,K] row-major (NT). TB==1: B is [K,N] (NN). M,N %128==0, K%8==0.
// DUAL: blockIdx.z==1 switches to (dA,dB,dBias,dC) — pairs two independent GEMMs.
template<int TB, bool RELU, bool ACC, bool DUAL>
__global__ __launch_bounds__(256) void gemm_kernel(
    const float* __restrict__ A, int lda, long long strideA,
    const float* __restrict__ B, int ldb, long long strideB,
    float* __restrict__ C, int ldc, long long strideC,
    int M, int N, int K,
    const float* __restrict__ bias, const float* __restrict__ bias2,
    const int* __restrict__ rowmask,
    const float* __restrict__ dA, const float* __restrict__ dB,
    const float* __restrict__ dBias, float* __restrict__ dC)
{
    __shared__ __align__(16) float As[2][8][128];
    __shared__ __align__(16) float Bs[2][8][128];

    const int tid = threadIdx.x;
    const int m0 = blockIdx.y * 128;
    const int n0 = blockIdx.x * 128;
    if (DUAL) {
        if (blockIdx.z == 1) { A = dA; B = dB; bias = dBias; C = dC; }
    } else {
        A += (long long)blockIdx.z * strideA;
        B += (long long)blockIdx.z * strideB;
        C += (long long)blockIdx.z * strideC;
    }

    const int ar   = tid >> 1;
    const int aseg = (tid & 1) * 4;
    const int bk   = tid >> 5;
    const int bn   = (tid & 31) * 4;
    const int nk   = K >> 3;

    {
        float4 a4 = *(const float4*)(A + (size_t)(m0 + ar) * lda + aseg);
        As[0][aseg + 0][ar] = a4.x; As[0][aseg + 1][ar] = a4.y;
        As[0][aseg + 2][ar] = a4.z; As[0][aseg + 3][ar] = a4.w;
        if (TB == 0) {
            float4 b4 = *(const float4*)(B + (size_t)(n0 + ar) * ldb + aseg);
            Bs[0][aseg + 0][ar] = b4.x; Bs[0][aseg + 1][ar] = b4.y;
            Bs[0][aseg + 2][ar] = b4.z; Bs[0][aseg + 3][ar] = b4.w;
        } else {
            *(float4*)&Bs[0][bk][bn] = *(const float4*)(B + (size_t)bk * ldb + n0 + bn);
        }
    }
    __syncthreads();

    float acc[8][8];
    #pragma unroll
    for (int i = 0; i < 8; i++)
        #pragma unroll
        for (int j = 0; j < 8; j++) acc[i][j] = 0.f;

    const int tm = (tid >> 4) << 3;
    const int tn = (tid & 15) << 3;

    for (int kt = 0; kt < nk; ++kt) {
        const int cur = kt & 1, nxt = cur ^ 1;
        float4 na, nb;
        if (kt + 1 < nk) {
            const int k0 = (kt + 1) << 3;
            na = *(const float4*)(A + (size_t)(m0 + ar) * lda + k0 + aseg);
            if (TB == 0)
                nb = *(const float4*)(B + (size_t)(n0 + ar) * ldb + k0 + aseg);
            else
                nb = *(const float4*)(B + (size_t)(k0 + bk) * ldb + n0 + bn);
        }
        #pragma unroll
        for (int kk = 0; kk < 8; ++kk) {
            float4 aa0 = *(const float4*)&As[cur][kk][tm];
            float4 aa1 = *(const float4*)&As[cur][kk][tm + 4];
            float4 bb0 = *(const float4*)&Bs[cur][kk][tn];
            float4 bb1 = *(const float4*)&Bs[cur][kk][tn + 4];
            float av_[8] = {aa0.x, aa0.y, aa0.z, aa0.w, aa1.x, aa1.y, aa1.z, aa1.w};
            float bv_[8] = {bb0.x, bb0.y, bb0.z, bb0.w, bb1.x, bb1.y, bb1.z, bb1.w};
            #pragma unroll
            for (int i = 0; i < 8; i++)
                #pragma unroll
                for (int j = 0; j < 8; j++)
                    acc[i][j] = fmaf(av_[i], bv_[j], acc[i][j]);
        }
        if (kt + 1 < nk) {
            As[nxt][aseg + 0][ar] = na.x; As[nxt][aseg + 1][ar] = na.y;
            As[nxt][aseg + 2][ar] = na.z; As[nxt][aseg + 3][ar] = na.w;
            if (TB == 0) {
                Bs[nxt][aseg + 0][ar] = nb.x; Bs[nxt][aseg + 1][ar] = nb.y;
                Bs[nxt][aseg + 2][ar] = nb.z; Bs[nxt][aseg + 3][ar] = nb.w;
            } else {
                *(float4*)&Bs[nxt][bk][bn] = nb;
            }
        }
        __syncthreads();
    }

    float bvv[8];
    #pragma unroll
    for (int j = 0; j < 8; j++) {
        float b = bias ? bias[n0 + tn + j] : 0.f;
        if (bias2) b += bias2[n0 + tn + j];
        bvv[j] = b;
    }
    #pragma unroll
    for (int i = 0; i < 8; i++) {
        const int row = m0 + tm + i;
        float keep = 1.f;
        if (rowmask) keep = rowmask[row] ? 1.f : 0.f;
        float out[8];
        #pragma unroll
        for (int j = 0; j < 8; j++) {
            float v = acc[i][j] + bvv[j];
            if (RELU) v = fmaxf(v, 0.f);
            out[j] = v * keep;
        }
        float* Cp = C + (size_t)row * ldc + n0 + tn;
        if (ACC) {
            float4 o0 = *(const float4*)Cp;
            float4 o1 = *(const float4*)(Cp + 4);
            out[0] += o0.x; out[1] += o0.y; out[2] += o0.z; out[3] += o0.w;
            out[4] += o1.x; out[5] += o1.y; out[6] += o1.z; out[7] += o1.w;
        }
        *(float4*)Cp       = make_float4(out[0], out[1], out[2], out[3]);
        *(float4*)(Cp + 4) = make_float4(out[4], out[5], out[6], out[7]);
    }
}

// ---------- masked softmax per row (in place) + has-neighbor flag ----------
__global__ __launch_bounds__(256) void softmax_kernel(
    float* __restrict__ S, const int* __restrict__ adj, int* __restrict__ hasnb)
{
    __shared__ float sred[32];
    const int r = blockIdx.x;
    const int i = r & 1023;
    const int tid = threadIdx.x;
    float* Sr = S + (size_t)r * 1024;
    const int* Ar = adj + (size_t)r * 1024;

    float v[4]; int ok[4];
    float mx = -3.0e38f;
    #pragma unroll
    for (int q = 0; q < 4; q++) {
        int j = tid + 256 * q;
        ok[q] = (Ar[j] > 0) && (j != i);
        v[q] = Sr[j];
        if (ok[q]) mx = fmaxf(mx, v[q]);
    }
    #pragma unroll
    for (int off = 16; off > 0; off >>= 1)
        mx = fmaxf(mx, __shfl_xor_sync(0xffffffffu, mx, off));
    if ((tid & 31) == 0) sred[tid >> 5] = mx;
    __syncthreads();
    if (tid < 32) {
        float m2 = (tid < 8) ? sred[tid] : -3.0e38f;
        #pragma unroll
        for (int off = 4; off > 0; off >>= 1)
            m2 = fmaxf(m2, __shfl_xor_sync(0xffffffffu, m2, off));
        if (tid == 0) sred[0] = m2;
    }
    __syncthreads();
    const float rowmax = sred[0];
    const bool any = rowmax > -1.0e37f;

    float e[4];
    float s = 0.f;
    #pragma unroll
    for (int q = 0; q < 4; q++) {
        e[q] = ok[q] ? expf(v[q] - rowmax) : 0.f;
        s += e[q];
    }
    #pragma unroll
    for (int off = 16; off > 0; off >>= 1)
        s += __shfl_xor_sync(0xffffffffu, s, off);
    __syncthreads();
    if ((tid & 31) == 0) sred[tid >> 5] = s;
    __syncthreads();
    if (tid < 32) {
        float s2 = (tid < 8) ? sred[tid] : 0.f;
        #pragma unroll
        for (int off = 4; off > 0; off >>= 1)
            s2 += __shfl_xor_sync(0xffffffffu, s2, off);
        if (tid == 0) sred[0] = s2;
    }
    __syncthreads();
    const float inv = any ? (1.f / sred[0]) : 0.f;
    #pragma unroll
    for (int q = 0; q < 4; q++)
        Sr[tid + 256 * q] = e[q] * inv;
    if (tid == 0) hasnb[r] = any ? 1 : 0;
}

extern "C" void kernel_launch(void* const* d_in, const int* in_sizes, int n_in,
                              void* d_out, int out_size)
{
    const float* feats  = (const float*)d_in[0];
    const int*   adj    = (const int*)  d_in[1];
    const float* W_ih   = (const float*)d_in[2];
    const float* W_hh   = (const float*)d_in[3];
    const float* b_ih   = (const float*)d_in[4];
    const float* b_hh   = (const float*)d_in[5];
    const float* gx_W1  = (const float*)d_in[6];
    const float* gx_b1  = (const float*)d_in[7];
    const float* gx_W2  = (const float*)d_in[8];
    const float* gx_b2  = (const float*)d_in[9];
    const float* gz_W1  = (const float*)d_in[10];
    const float* gz_b1  = (const float*)d_in[11];
    const float* gz_W2  = (const float*)d_in[12];
    const float* gz_b2  = (const float*)d_in[13];
    const float* gv_W1  = (const float*)d_in[14];
    const float* gv_b1  = (const float*)d_in[15];
    const float* gv_W2  = (const float*)d_in[16];
    const float* gv_b2  = (const float*)d_in[17];
    const float* gn_W1  = (const float*)d_in[18];
    const float* gn_b1  = (const float*)d_in[19];
    const float* gn_W2  = (const float*)d_in[20];
    const float* gn_b2  = (const float*)d_in[21];
    const float* out_W  = (const float*)d_in[22];
    const float* out_b  = (const float*)d_in[23];
    float* out = (float*)d_out;

    float *xproj, *h, *t1, *t2, *t3, *ax, *av, *scores, *sagg, *agg;
    int* hasnb;
    cudaGetSymbolAddress((void**)&xproj,  g_xproj);
    cudaGetSymbolAddress((void**)&h,      g_h);
    cudaGetSymbolAddress((void**)&t1,     g_t1);
    cudaGetSymbolAddress((void**)&t2,     g_t2);
    cudaGetSymbolAddress((void**)&t3,     g_t3);
    cudaGetSymbolAddress((void**)&ax,     g_ax);
    cudaGetSymbolAddress((void**)&av,     g_av);
    cudaGetSymbolAddress((void**)&scores, g_scores);
    cudaGetSymbolAddress((void**)&sagg,   g_sagg);
    cudaGetSymbolAddress((void**)&agg,    g_agg);
    cudaGetSymbolAddress((void**)&hasnb,  g_hasnb);

    reset_kernel<<<1, 128>>>();

    // x_proj = feats @ W_ih^T + (b_ih + b_hh) : [8192,2048], K=256
    gemm_kernel<0, false, false, false><<<dim3(16, 64, 1), 256>>>(
        feats, 256, 0, W_ih, 256, 0, xproj, 2048, 0,
        8192, 2048, 256, b_ih, b_hh, nullptr,
        nullptr, nullptr, nullptr, nullptr);

    lstm_kernel<<<128, 256>>>(W_hh);

    // ax/av MLP layer 1 (paired): h@gx_W1^T->t1 ; h@gv_W1^T->t3
    gemm_kernel<0, true , false, true><<<dim3(2, 64, 2), 256>>>(
        h, 512, 0, gx_W1, 512, 0, t1, 256, 0, 8192, 256, 512, gx_b1, nullptr, nullptr,
        h, gv_W1, gv_b1, t3);
    // ax/av MLP layer 2 (paired): t1@gx_W2^T->ax ; t3@gv_W2^T->av
    gemm_kernel<0, false, false, true><<<dim3(2, 64, 2), 256>>>(
        t1, 256, 0, gx_W2, 256, 0, ax, 256, 0, 8192, 256, 256, gx_b2, nullptr, nullptr,
        t3, gv_W2, gv_b2, av);

    // scores[b] = ax[b] @ av[b]^T
    gemm_kernel<0, false, false, false><<<dim3(8, 8, 8), 256>>>(
        ax, 256, 1024LL * 256, av, 256, 1024LL * 256,
        scores, 1024, 1024LL * 1024, 1024, 1024, 256, nullptr, nullptr, nullptr,
        nullptr, nullptr, nullptr, nullptr);

    softmax_kernel<<<8192, 256>>>(scores, adj, hasnb);

    // sagg[b] = w[b] @ h[b]
    gemm_kernel<1, false, false, false><<<dim3(4, 8, 8), 256>>>(
        scores, 1024, 1024LL * 1024, h, 512, 1024LL * 512,
        sagg, 512, 1024LL * 512, 1024, 512, 1024, nullptr, nullptr, nullptr,
        nullptr, nullptr, nullptr, nullptr);

    // agg = MLP_gn(MLP_gz(sagg)) with isolated-node zeroing
    gemm_kernel<0, true , false, false><<<dim3(2, 64, 1), 256>>>(
        sagg, 512, 0, gz_W1, 512, 0, t1, 256, 0, 8192, 256, 512, gz_b1, nullptr, nullptr,
        nullptr, nullptr, nullptr, nullptr);
    gemm_kernel<0, false, false, false><<<dim3(2, 64, 1), 256>>>(
        t1, 256, 0, gz_W2, 256, 0, t2, 256, 0, 8192, 256, 256, gz_b2, nullptr, nullptr,
        nullptr, nullptr, nullptr, nullptr);
    gemm_kernel<0, true , false, false><<<dim3(2, 64, 1), 256>>>(
        t2, 256, 0, gn_W1, 256, 0, t1, 256, 0, 8192, 256, 256, gn_b1, nullptr, nullptr,
        nullptr, nullptr, nullptr, nullptr);
    gemm_kernel<0, false, false, false><<<dim3(2, 64, 1), 256>>>(
        t1, 256, 0, gn_W2, 256, 0, agg, 256, 0, 8192, 256, 256, gn_b2, nullptr, hasnb,
        nullptr, nullptr, nullptr, nullptr);

    // out = h @ out_W[:, :512]^T + out_b ; out += agg @ out_W[:, 512:]^T
    gemm_kernel<0, false, false, false><<<dim3(2, 64, 1), 256>>>(
        h, 512, 0, out_W, 768, 0, out, 256, 0, 8192, 256, 512, out_b, nullptr, nullptr,
        nullptr, nullptr, nullptr, nullptr);
    gemm_kernel<0, false, true , false><<<dim3(2, 64, 1), 256>>>(
        agg, 256, 0, out_W + 512, 768, 0, out, 256, 0, 8192, 256, 256, nullptr, nullptr, nullptr,
        nullptr, nullptr, nullptr, nullptr);
}

// round 7
// speedup vs baseline: 2.0504x; 2.0504x over previous
#include <cuda_runtime.h>

// B=8, N=1024, D=256, H=512, M=256, O=256, 4H=2048

__device__ float g_xproj[8 * 1024 * 2048];
__device__ float g_h    [8 * 1024 * 512];
__device__ float g_t1   [8 * 1024 * 256];
__device__ float g_t2   [8 * 1024 * 256];
__device__ float g_t3   [8 * 1024 * 256];
__device__ float g_ax   [8 * 1024 * 256];
__device__ float g_av   [8 * 1024 * 256];
__device__ float g_scores[8 * 1024 * 1024];
__device__ float g_sagg [8 * 1024 * 512];
__device__ float g_agg  [8 * 1024 * 256];
__device__ int   g_hasnb[8 * 1024];
__device__ unsigned g_ctr[1024];

__device__ __forceinline__ unsigned ld_acq(const unsigned* p) {
    unsigned v;
    asm volatile("ld.acquire.gpu.global.u32 %0, [%1];" : "=r"(v) : "l"(p) : "memory");
    return v;
}
__device__ __forceinline__ void red_rel_add(unsigned* p, unsigned v) {
    asm volatile("red.add.release.gpu.global.u32 [%0], %1;" :: "l"(p), "r"(v) : "memory");
}
__device__ __forceinline__ unsigned long long pk2(float lo, float hi) {
    unsigned long long r;
    asm("mov.b64 %0, {%1, %2};" : "=l"(r) : "f"(lo), "f"(hi));
    return r;
}
__device__ __forceinline__ void fma2(unsigned long long& d, unsigned long long a, unsigned long long b) {
    asm("fma.rn.f32x2 %0, %1, %2, %0;" : "+l"(d) : "l"(a), "l"(b));
}
__device__ __forceinline__ float unpk_sum(unsigned long long v) {
    float x, y;
    asm("mov.b64 {%0, %1}, %2;" : "=f"(x), "=f"(y) : "l"(v));
    return x + y;
}
__device__ __forceinline__ float sigf(float x) {
    return __fdividef(1.f, 1.f + __expf(-x));
}
__device__ __forceinline__ float tanhfast(float x) {
    return __fdividef(2.f, 1.f + __expf(-2.f * x)) - 1.f;
}

__global__ void reset_kernel() {
    g_ctr[threadIdx.x] = 0u;
}

// ---------- persistent LSTM: 128 CTAs x 256 thr; CTA owns 4 j-cols (16 gate rows) ----------
// k layout per lane: k = 4*lane + 128*i (i=0..3); f32x2 packed math throughout.
// Sync: per-step arrival counter g_ctr[t]; producers red.release, one lane spins.
__global__ __launch_bounds__(256, 1) void lstm_kernel(const float* __restrict__ Whh)
{
    __shared__ __align__(16) float hs[8 * 512];
    __shared__ float gsum[16][8];

    const int tid  = threadIdx.x;
    const int w    = tid >> 5;
    const int lane = tid & 31;
    const int j0   = blockIdx.x * 4;

    unsigned long long wp0[8], wp1[8];
    {
        int lr0 = 2 * w, lr1 = 2 * w + 1;
        int grow0 = (lr0 >> 2) * 512 + j0 + (lr0 & 3);
        int grow1 = (lr1 >> 2) * 512 + j0 + (lr1 & 3);
        #pragma unroll
        for (int i = 0; i < 4; i++) {
            int k = 4 * lane + 128 * i;
            float4 a = *(const float4*)&Whh[(size_t)grow0 * 512 + k];
            float4 b = *(const float4*)&Whh[(size_t)grow1 * 512 + k];
            wp0[2 * i]     = pk2(a.x, a.y);
            wp0[2 * i + 1] = pk2(a.z, a.w);
            wp1[2 * i]     = pk2(b.x, b.y);
            wp1[2 * i + 1] = pk2(b.z, b.w);
        }
    }

    float c_st = 0.f;
    const int ub  = lane >> 2;   // batch for update lanes
    const int ujl = lane & 3;    // local j for update lanes

    for (int t = 0; t < 1024; ++t) {
        // prefetch x-projection gate inputs (independent of h[t-1])
        float xq0 = 0.f, xq1 = 0.f, xq2 = 0.f, xq3 = 0.f;
        if (tid < 32) {
            size_t base = ((size_t)(ub << 10) + t) * 2048 + j0 + ujl;
            xq0 = g_xproj[base];
            xq1 = g_xproj[base + 512];
            xq2 = g_xproj[base + 1024];
            xq3 = g_xproj[base + 1536];
        }

        // single-lane wait for all 128 CTAs to have published h[t-1]
        if (t > 0 && tid == 0) {
            while (ld_acq(&g_ctr[t - 1]) < 128u) { }
        }
        __syncthreads();

        if (t == 0) {
            #pragma unroll
            for (int q = 0; q < 4; q++)
                *(float4*)&hs[(tid + 256 * q) * 4] = make_float4(0.f, 0.f, 0.f, 0.f);
        } else {
            #pragma unroll
            for (int q = 0; q < 4; q++) {
                int flat = (tid + 256 * q) * 4;
                int b = flat >> 9, k = flat & 511;
                *(float4*)&hs[flat] =
                    *(const float4*)&g_h[((size_t)(b << 10) + (t - 1)) * 512 + k];
            }
        }
        __syncthreads();

        // matvec: 2 rows x 8 batches, f32x2 packed
        unsigned long long acc0[8], acc1[8];
        #pragma unroll
        for (int b = 0; b < 8; b++) { acc0[b] = 0ull; acc1[b] = 0ull; }
        #pragma unroll
        for (int i = 0; i < 4; i++) {
            const int kb = 4 * lane + 128 * i;
            const unsigned long long w00 = wp0[2 * i], w01 = wp0[2 * i + 1];
            const unsigned long long w10 = wp1[2 * i], w11 = wp1[2 * i + 1];
            #pragma unroll
            for (int b = 0; b < 8; b++) {
                ulonglong2 hv = *(const ulonglong2*)&hs[b * 512 + kb];
                fma2(acc0[b], w00, hv.x);
                fma2(acc0[b], w01, hv.y);
                fma2(acc1[b], w10, hv.x);
                fma2(acc1[b], w11, hv.y);
            }
        }

        float a0[8], a1[8];
        #pragma unroll
        for (int b = 0; b < 8; b++) { a0[b] = unpk_sum(acc0[b]); a1[b] = unpk_sum(acc1[b]); }

        // folded butterfly: masks 16,8,4 fold b (8->4->2->1), masks 2,1 finish reduce
        float r0[8], r1[8];
        #pragma unroll
        for (int b = 0; b < 8; b++) {
            r0[b] = __shfl_xor_sync(0xffffffffu, a0[b], 16);
            r1[b] = __shfl_xor_sync(0xffffffffu, a1[b], 16);
        }
        const int h16 = (lane & 16) ? 4 : 0;
        float c0[4], c1[4];
        #pragma unroll
        for (int j = 0; j < 4; j++) {
            c0[j] = a0[h16 + j] + r0[h16 + j];
            c1[j] = a1[h16 + j] + r1[h16 + j];
        }
        float d0[4], d1[4];
        #pragma unroll
        for (int j = 0; j < 4; j++) {
            d0[j] = __shfl_xor_sync(0xffffffffu, c0[j], 8);
            d1[j] = __shfl_xor_sync(0xffffffffu, c1[j], 8);
        }
        const int h8 = (lane & 8) ? 2 : 0;
        float e0[2], e1[2];
        #pragma unroll
        for (int j = 0; j < 2; j++) {
            e0[j] = c0[h8 + j] + d0[h8 + j];
            e1[j] = c1[h8 + j] + d1[h8 + j];
        }
        float q00 = __shfl_xor_sync(0xffffffffu, e0[0], 4);
        float q01 = __shfl_xor_sync(0xffffffffu, e0[1], 4);
        float q10 = __shfl_xor_sync(0xffffffffu, e1[0], 4);
        float q11 = __shfl_xor_sync(0xffffffffu, e1[1], 4);
        float s0 = (lane & 4) ? (e0[1] + q01) : (e0[0] + q00);
        float s1 = (lane & 4) ? (e1[1] + q11) : (e1[0] + q10);
        s0 += __shfl_xor_sync(0xffffffffu, s0, 2);
        s0 += __shfl_xor_sync(0xffffffffu, s0, 1);
        s1 += __shfl_xor_sync(0xffffffffu, s1, 2);
        s1 += __shfl_xor_sync(0xffffffffu, s1, 1);
        const int bidx = (lane >> 2) & 7;
        if ((lane & 3) == 0)      gsum[2 * w][bidx]     = s0;
        else if ((lane & 3) == 1) gsum[2 * w + 1][bidx] = s1;
        __syncthreads();

        if (tid < 32) {
            float gi = gsum[0  + ujl][ub] + xq0;
            float gf = gsum[4  + ujl][ub] + xq1;
            float gg = gsum[8  + ujl][ub] + xq2;
            float go = gsum[12 + ujl][ub] + xq3;
            float si = sigf(gi);
            float sf = sigf(gf);
            float so = sigf(go);
            float tg = tanhfast(gg);
            c_st = sf * c_st + si * tg;
            float hN = so * tanhfast(c_st);
            g_h[((size_t)(ub << 10) + t) * 512 + j0 + ujl] = hN;
            __syncwarp();
            if (lane == 0) red_rel_add(&g_ctr[t], 1u);
        }
    }
}

// ---------- generic tiled fp32 GEMM: C = A @ op(B) (+bias[+bias2]) [ReLU] [ACC] [rowmask] ----------
// TB==0: B is [N,K] row-major (NT). TB==1: B is [K,N] (NN). M,N %128==0, K%8==0.
// DUAL: blockIdx.z==1 switches to (dA,dB,dBias,dC) — pairs two independent GEMMs.
template<int TB, bool RELU, bool ACC, bool DUAL>
__global__ __launch_bounds__(256) void gemm_kernel(
    const float* __restrict__ A, int lda, long long strideA,
    const float* __restrict__ B, int ldb, long long strideB,
    float* __restrict__ C, int ldc, long long strideC,
    int M, int N, int K,
    const float* __restrict__ bias, const float* __restrict__ bias2,
    const int* __restrict__ rowmask,
    const float* __restrict__ dA, const float* __restrict__ dB,
    const float* __restrict__ dBias, float* __restrict__ dC)
{
    __shared__ __align__(16) float As[2][8][128];
    __shared__ __align__(16) float Bs[2][8][128];

    const int tid = threadIdx.x;
    const int m0 = blockIdx.y * 128;
    const int n0 = blockIdx.x * 128;
    if (DUAL) {
        if (blockIdx.z == 1) { A = dA; B = dB; bias = dBias; C = dC; }
    } else {
        A += (long long)blockIdx.z * strideA;
        B += (long long)blockIdx.z * strideB;
        C += (long long)blockIdx.z * strideC;
    }

    const int ar   = tid >> 1;
    const int aseg = (tid & 1) * 4;
    const int bk   = tid >> 5;
    const int bn   = (tid & 31) * 4;
    const int nk   = K >> 3;

    {
        float4 a4 = *(const float4*)(A + (size_t)(m0 + ar) * lda + aseg);
        As[0][aseg + 0][ar] = a4.x; As[0][aseg + 1][ar] = a4.y;
        As[0][aseg + 2][ar] = a4.z; As[0][aseg + 3][ar] = a4.w;
        if (TB == 0) {
            float4 b4 = *(const float4*)(B + (size_t)(n0 + ar) * ldb + aseg);
            Bs[0][aseg + 0][ar] = b4.x; Bs[0][aseg + 1][ar] = b4.y;
            Bs[0][aseg + 2][ar] = b4.z; Bs[0][aseg + 3][ar] = b4.w;
        } else {
            *(float4*)&Bs[0][bk][bn] = *(const float4*)(B + (size_t)bk * ldb + n0 + bn);
        }
    }
    __syncthreads();

    float acc[8][8];
    #pragma unroll
    for (int i = 0; i < 8; i++)
        #pragma unroll
        for (int j = 0; j < 8; j++) acc[i][j] = 0.f;

    const int tm = (tid >> 4) << 3;
    const int tn = (tid & 15) << 3;

    for (int kt = 0; kt < nk; ++kt) {
        const int cur = kt & 1, nxt = cur ^ 1;
        float4 na, nb;
        if (kt + 1 < nk) {
            const int k0 = (kt + 1) << 3;
            na = *(const float4*)(A + (size_t)(m0 + ar) * lda + k0 + aseg);
            if (TB == 0)
                nb = *(const float4*)(B + (size_t)(n0 + ar) * ldb + k0 + aseg);
            else
                nb = *(const float4*)(B + (size_t)(k0 + bk) * ldb + n0 + bn);
        }
        #pragma unroll
        for (int kk = 0; kk < 8; ++kk) {
            float4 aa0 = *(const float4*)&As[cur][kk][tm];
            float4 aa1 = *(const float4*)&As[cur][kk][tm + 4];
            float4 bb0 = *(const float4*)&Bs[cur][kk][tn];
            float4 bb1 = *(const float4*)&Bs[cur][kk][tn + 4];
            float av_[8] = {aa0.x, aa0.y, aa0.z, aa0.w, aa1.x, aa1.y, aa1.z, aa1.w};
            float bv_[8] = {bb0.x, bb0.y, bb0.z, bb0.w, bb1.x, bb1.y, bb1.z, bb1.w};
            #pragma unroll
            for (int i = 0; i < 8; i++)
                #pragma unroll
                for (int j = 0; j < 8; j++)
                    acc[i][j] = fmaf(av_[i], bv_[j], acc[i][j]);
        }
        if (kt + 1 < nk) {
            As[nxt][aseg + 0][ar] = na.x; As[nxt][aseg + 1][ar] = na.y;
            As[nxt][aseg + 2][ar] = na.z; As[nxt][aseg + 3][ar] = na.w;
            if (TB == 0) {
                Bs[nxt][aseg + 0][ar] = nb.x; Bs[nxt][aseg + 1][ar] = nb.y;
                Bs[nxt][aseg + 2][ar] = nb.z; Bs[nxt][aseg + 3][ar] = nb.w;
            } else {
                *(float4*)&Bs[nxt][bk][bn] = nb;
            }
        }
        __syncthreads();
    }

    float bvv[8];
    #pragma unroll
    for (int j = 0; j < 8; j++) {
        float b = bias ? bias[n0 + tn + j] : 0.f;
        if (bias2) b += bias2[n0 + tn + j];
        bvv[j] = b;
    }
    #pragma unroll
    for (int i = 0; i < 8; i++) {
        const int row = m0 + tm + i;
        float keep = 1.f;
        if (rowmask) keep = rowmask[row] ? 1.f : 0.f;
        float out[8];
        #pragma unroll
        for (int j = 0; j < 8; j++) {
            float v = acc[i][j] + bvv[j];
            if (RELU) v = fmaxf(v, 0.f);
            out[j] = v * keep;
        }
        float* Cp = C + (size_t)row * ldc + n0 + tn;
        if (ACC) {
            float4 o0 = *(const float4*)Cp;
            float4 o1 = *(const float4*)(Cp + 4);
            out[0] += o0.x; out[1] += o0.y; out[2] += o0.z; out[3] += o0.w;
            out[4] += o1.x; out[5] += o1.y; out[6] += o1.z; out[7] += o1.w;
        }
        *(float4*)Cp       = make_float4(out[0], out[1], out[2], out[3]);
        *(float4*)(Cp + 4) = make_float4(out[4], out[5], out[6], out[7]);
    }
}

// ---------- masked softmax per row (in place) + has-neighbor flag ----------
__global__ __launch_bounds__(256) void softmax_kernel(
    float* __restrict__ S, const int* __restrict__ adj, int* __restrict__ hasnb)
{
    __shared__ float sred[32];
    const int r = blockIdx.x;
    const int i = r & 1023;
    const int tid = threadIdx.x;
    float* Sr = S + (size_t)r * 1024;
    const int* Ar = adj + (size_t)r * 1024;

    float v[4]; int ok[4];
    float mx = -3.0e38f;
    #pragma unroll
    for (int q = 0; q < 4; q++) {
        int j = tid + 256 * q;
        ok[q] = (Ar[j] > 0) && (j != i);
        v[q] = Sr[j];
        if (ok[q]) mx = fmaxf(mx, v[q]);
    }
    #pragma unroll
    for (int off = 16; off > 0; off >>= 1)
        mx = fmaxf(mx, __shfl_xor_sync(0xffffffffu, mx, off));
    if ((tid & 31) == 0) sred[tid >> 5] = mx;
    __syncthreads();
    if (tid < 32) {
        float m2 = (tid < 8) ? sred[tid] : -3.0e38f;
        #pragma unroll
        for (int off = 4; off > 0; off >>= 1)
            m2 = fmaxf(m2, __shfl_xor_sync(0xffffffffu, m2, off));
        if (tid == 0) sred[0] = m2;
    }
    __syncthreads();
    const float rowmax = sred[0];
    const bool any = rowmax > -1.0e37f;

    float e[4];
    float s = 0.f;
    #pragma unroll
    for (int q = 0; q < 4; q++) {
        e[q] = ok[q] ? expf(v[q] - rowmax) : 0.f;
        s += e[q];
    }
    #pragma unroll
    for (int off = 16; off > 0; off >>= 1)
        s += __shfl_xor_sync(0xffffffffu, s, off);
    __syncthreads();
    if ((tid & 31) == 0) sred[tid >> 5] = s;
    __syncthreads();
    if (tid < 32) {
        float s2 = (tid < 8) ? sred[tid] : 0.f;
        #pragma unroll
        for (int off = 4; off > 0; off >>= 1)
            s2 += __shfl_xor_sync(0xffffffffu, s2, off);
        if (tid == 0) sred[0] = s2;
    }
    __syncthreads();
    const float inv = any ? (1.f / sred[0]) : 0.f;
    #pragma unroll
    for (int q = 0; q < 4; q++)
        Sr[tid + 256 * q] = e[q] * inv;
    if (tid == 0) hasnb[r] = any ? 1 : 0;
}

extern "C" void kernel_launch(void* const* d_in, const int* in_sizes, int n_in,
                              void* d_out, int out_size)
{
    const float* feats  = (const float*)d_in[0];
    const int*   adj    = (const int*)  d_in[1];
    const float* W_ih   = (const float*)d_in[2];
    const float* W_hh   = (const float*)d_in[3];
    const float* b_ih   = (const float*)d_in[4];
    const float* b_hh   = (const float*)d_in[5];
    const float* gx_W1  = (const float*)d_in[6];
    const float* gx_b1  = (const float*)d_in[7];
    const float* gx_W2  = (const float*)d_in[8];
    const float* gx_b2  = (const float*)d_in[9];
    const float* gz_W1  = (const float*)d_in[10];
    const float* gz_b1  = (const float*)d_in[11];
    const float* gz_W2  = (const float*)d_in[12];
    const float* gz_b2  = (const float*)d_in[13];
    const float* gv_W1  = (const float*)d_in[14];
    const float* gv_b1  = (const float*)d_in[15];
    const float* gv_W2  = (const float*)d_in[16];
    const float* gv_b2  = (const float*)d_in[17];
    const float* gn_W1  = (const float*)d_in[18];
    const float* gn_b1  = (const float*)d_in[19];
    const float* gn_W2  = (const float*)d_in[20];
    const float* gn_b2  = (const float*)d_in[21];
    const float* out_W  = (const float*)d_in[22];
    const float* out_b  = (const float*)d_in[23];
    float* out = (float*)d_out;

    float *xproj, *h, *t1, *t2, *t3, *ax, *av, *scores, *sagg, *agg;
    int* hasnb;
    cudaGetSymbolAddress((void**)&xproj,  g_xproj);
    cudaGetSymbolAddress((void**)&h,      g_h);
    cudaGetSymbolAddress((void**)&t1,     g_t1);
    cudaGetSymbolAddress((void**)&t2,     g_t2);
    cudaGetSymbolAddress((void**)&t3,     g_t3);
    cudaGetSymbolAddress((void**)&ax,     g_ax);
    cudaGetSymbolAddress((void**)&av,     g_av);
    cudaGetSymbolAddress((void**)&scores, g_scores);
    cudaGetSymbolAddress((void**)&sagg,   g_sagg);
    cudaGetSymbolAddress((void**)&agg,    g_agg);
    cudaGetSymbolAddress((void**)&hasnb,  g_hasnb);

    reset_kernel<<<1, 1024>>>();

    // x_proj = feats @ W_ih^T + (b_ih + b_hh) : [8192,2048], K=256
    gemm_kernel<0, false, false, false><<<dim3(16, 64, 1), 256>>>(
        feats, 256, 0, W_ih, 256, 0, xproj, 2048, 0,
        8192, 2048, 256, b_ih, b_hh, nullptr,
        nullptr, nullptr, nullptr, nullptr);

    lstm_kernel<<<128, 256>>>(W_hh);

    // ax/av MLP layer 1 (paired): h@gx_W1^T->t1 ; h@gv_W1^T->t3
    gemm_kernel<0, true , false, true><<<dim3(2, 64, 2), 256>>>(
        h, 512, 0, gx_W1, 512, 0, t1, 256, 0, 8192, 256, 512, gx_b1, nullptr, nullptr,
        h, gv_W1, gv_b1, t3);
    // ax/av MLP layer 2 (paired): t1@gx_W2^T->ax ; t3@gv_W2^T->av
    gemm_kernel<0, false, false, true><<<dim3(2, 64, 2), 256>>>(
        t1, 256, 0, gx_W2, 256, 0, ax, 256, 0, 8192, 256, 256, gx_b2, nullptr, nullptr,
        t3, gv_W2, gv_b2, av);

    // scores[b] = ax[b] @ av[b]^T
    gemm_kernel<0, false, false, false><<<dim3(8, 8, 8), 256>>>(
        ax, 256, 1024LL * 256, av, 256, 1024LL * 256,
        scores, 1024, 1024LL * 1024, 1024, 1024, 256, nullptr, nullptr, nullptr,
        nullptr, nullptr, nullptr, nullptr);

    softmax_kernel<<<8192, 256>>>(scores, adj, hasnb);

    // sagg[b] = w[b] @ h[b]
    gemm_kernel<1, false, false, false><<<dim3(4, 8, 8), 256>>>(
        scores, 1024, 1024LL * 1024, h, 512, 1024LL * 512,
        sagg, 512, 1024LL * 512, 1024, 512, 1024, nullptr, nullptr, nullptr,
        nullptr, nullptr, nullptr, nullptr);

    // agg = MLP_gn(MLP_gz(sagg)) with isolated-node zeroing
    gemm_kernel<0, true , false, false><<<dim3(2, 64, 1), 256>>>(
        sagg, 512, 0, gz_W1, 512, 0, t1, 256, 0, 8192, 256, 512, gz_b1, nullptr, nullptr,
        nullptr, nullptr, nullptr, nullptr);
    gemm_kernel<0, false, false, false><<<dim3(2, 64, 1), 256>>>(
        t1, 256, 0, gz_W2, 256, 0, t2, 256, 0, 8192, 256, 256, gz_b2, nullptr, nullptr,
        nullptr, nullptr, nullptr, nullptr);
    gemm_kernel<0, true , false, false><<<dim3(2, 64, 1), 256>>>(
        t2, 256, 0, gn_W1, 256, 0, t1, 256, 0, 8192, 256, 256, gn_b1, nullptr, nullptr,
        nullptr, nullptr, nullptr, nullptr);
    gemm_kernel<0, false, false, false><<<dim3(2, 64, 1), 256>>>(
        t1, 256, 0, gn_W2, 256, 0, agg, 256, 0, 8192, 256, 256, gn_b2, nullptr, hasnb,
        nullptr, nullptr, nullptr, nullptr);

    // out = h @ out_W[:, :512]^T + out_b ; out += agg @ out_W[:, 512:]^T
    gemm_kernel<0, false, false, false><<<dim3(2, 64, 1), 256>>>(
        h, 512, 0, out_W, 768, 0, out, 256, 0, 8192, 256, 512, out_b, nullptr, nullptr,
        nullptr, nullptr, nullptr, nullptr);
    gemm_kernel<0, false, true , false><<<dim3(2, 64, 1), 256>>>(
        agg, 256, 0, out_W + 512, 768, 0, out, 256, 0, 8192, 256, 256, nullptr, nullptr, nullptr,
        nullptr, nullptr, nullptr, nullptr);
}

// round 8
// speedup vs baseline: 2.0905x; 1.0195x over previous
#include <cuda_runtime.h>

// B=8, N=1024, D=256, H=512, M=256, O=256, 4H=2048

__device__ float g_xproj[8 * 1024 * 2048];
__device__ float g_h    [8 * 1024 * 512];
__device__ float g_t1   [8 * 1024 * 256];
__device__ float g_t2   [8 * 1024 * 256];
__device__ float g_t3   [8 * 1024 * 256];
__device__ float g_ax   [8 * 1024 * 256];
__device__ float g_av   [8 * 1024 * 256];
__device__ float g_scores[8 * 1024 * 1024];
__device__ float g_sagg [8 * 1024 * 512];
__device__ float g_agg  [8 * 1024 * 256];
__device__ int   g_hasnb[8 * 1024];
__device__ unsigned g_ctr[1024];

__device__ __forceinline__ unsigned ld_acq(const unsigned* p) {
    unsigned v;
    asm volatile("ld.acquire.gpu.global.u32 %0, [%1];" : "=r"(v) : "l"(p) : "memory");
    return v;
}
__device__ __forceinline__ void red_rel_add(unsigned* p, unsigned v) {
    asm volatile("red.add.release.gpu.global.u32 [%0], %1;" :: "l"(p), "r"(v) : "memory");
}
__device__ __forceinline__ unsigned long long pk2(float lo, float hi) {
    unsigned long long r;
    asm("mov.b64 %0, {%1, %2};" : "=l"(r) : "f"(lo), "f"(hi));
    return r;
}
__device__ __forceinline__ void fma2(unsigned long long& d, unsigned long long a, unsigned long long b) {
    asm("fma.rn.f32x2 %0, %1, %2, %0;" : "+l"(d) : "l"(a), "l"(b));
}
__device__ __forceinline__ float unpk_sum(unsigned long long v) {
    float x, y;
    asm("mov.b64 {%0, %1}, %2;" : "=f"(x), "=f"(y) : "l"(v));
    return x + y;
}
__device__ __forceinline__ float sigf(float x) {
    return __fdividef(1.f, 1.f + __expf(-x));
}
__device__ __forceinline__ float tanhfast(float x) {
    return __fdividef(2.f, 1.f + __expf(-2.f * x)) - 1.f;
}
__device__ __forceinline__ void barhalf(int half) {
    asm volatile("bar.sync %0, 128;" :: "r"(1 + half) : "memory");
}

__global__ void reset_kernel() {
    g_ctr[threadIdx.x] = 0u;
}

// ---------- persistent LSTM: 128 CTAs x 256 thr; CTA owns 4 j-cols (16 gate rows) ----------
// warp w: gate rw = w&3 (4 j-locals), batch group bw = w>>2 (4 batches).
// Half-CTA domains: tids 0-127 own batches 0-3 (hs[0:2048]), tids 128-255 own batches 4-7.
// k layout per lane: k = 4*lane + 128*i; f32x2 packed math.
__global__ __launch_bounds__(256, 1) void lstm_kernel(const float* __restrict__ Whh)
{
    __shared__ __align__(16) float hs[8 * 512];
    __shared__ float gsum[16][8];

    const int tid  = threadIdx.x;
    const int w    = tid >> 5;
    const int lane = tid & 31;
    const int j0   = blockIdx.x * 4;
    const int rw   = w & 3;    // gate
    const int bw   = w >> 2;   // batch group (0 or 1)
    const int half = tid >> 7;
    const int htid = tid & 127;

    // weights: 4 rows (gate rw, j-locals 0..3) x 16 k, packed f32x2
    unsigned long long wq[4][8];
    #pragma unroll
    for (int r = 0; r < 4; r++) {
        const size_t grow = (size_t)(rw * 512 + j0 + r) * 512;
        #pragma unroll
        for (int i = 0; i < 4; i++) {
            float4 a = *(const float4*)&Whh[grow + 4 * lane + 128 * i];
            wq[r][2 * i]     = pk2(a.x, a.y);
            wq[r][2 * i + 1] = pk2(a.z, a.w);
        }
    }

    float c_st = 0.f;
    const int ub  = lane >> 2;   // batch for update lanes
    const int ujl = lane & 3;    // local j for update lanes

    for (int t = 0; t < 1024; ++t) {
        // prefetch x-projection gate inputs (independent of h[t-1])
        float xq0 = 0.f, xq1 = 0.f, xq2 = 0.f, xq3 = 0.f;
        if (tid < 32) {
            size_t base = ((size_t)(ub << 10) + t) * 2048 + j0 + ujl;
            xq0 = g_xproj[base];
            xq1 = g_xproj[base + 512];
            xq2 = g_xproj[base + 1024];
            xq3 = g_xproj[base + 1536];
        }

        // one poller per half waits for all 128 CTAs to have published h[t-1]
        if (t > 0 && htid == 0) {
            while (ld_acq(&g_ctr[t - 1]) < 128u) { }
        }
        barhalf(half);

        // each half stages its own 4 batches of h (8KB)
        if (t == 0) {
            #pragma unroll
            for (int q = 0; q < 4; q++)
                *(float4*)&hs[(half * 512 + htid + 128 * q) * 4] =
                    make_float4(0.f, 0.f, 0.f, 0.f);
        } else {
            #pragma unroll
            for (int q = 0; q < 4; q++) {
                int flat = (half * 512 + htid + 128 * q) * 4;   // b*512 + k
                int b = flat >> 9, k = flat & 511;
                *(float4*)&hs[flat] =
                    *(const float4*)&g_h[((size_t)(b << 10) + (t - 1)) * 512 + k];
            }
        }
        barhalf(half);

        // matvec: 4 rows x 4 batches per warp
        unsigned long long acc[16];
        #pragma unroll
        for (int j = 0; j < 16; j++) acc[j] = 0ull;
        #pragma unroll
        for (int i = 0; i < 4; i++) {
            const int kb = 4 * lane + 128 * i;
            #pragma unroll
            for (int bb = 0; bb < 4; bb++) {
                ulonglong2 hv = *(const ulonglong2*)&hs[(4 * bw + bb) * 512 + kb];
                #pragma unroll
                for (int r = 0; r < 4; r++) {
                    fma2(acc[r * 4 + bb], wq[r][2 * i],     hv.x);
                    fma2(acc[r * 4 + bb], wq[r][2 * i + 1], hv.y);
                }
            }
        }

        float v[16];
        #pragma unroll
        for (int j = 0; j < 16; j++) v[j] = unpk_sum(acc[j]);

        // folded butterfly: bits 16,8,4,2 fold 16 values -> 1, bit 1 finishes k-reduce
        float t16[16];
        #pragma unroll
        for (int j = 0; j < 16; j++) t16[j] = __shfl_xor_sync(0xffffffffu, v[j], 16);
        const int s16 = (lane & 16) ? 8 : 0;
        float w8[8];
        #pragma unroll
        for (int j = 0; j < 8; j++) w8[j] = v[s16 + j] + t16[s16 + j];
        float t8[8];
        #pragma unroll
        for (int j = 0; j < 8; j++) t8[j] = __shfl_xor_sync(0xffffffffu, w8[j], 8);
        const int s8 = (lane & 8) ? 4 : 0;
        float w4[4];
        #pragma unroll
        for (int j = 0; j < 4; j++) w4[j] = w8[s8 + j] + t8[s8 + j];
        float t4[4];
        #pragma unroll
        for (int j = 0; j < 4; j++) t4[j] = __shfl_xor_sync(0xffffffffu, w4[j], 4);
        const int s4 = (lane & 4) ? 2 : 0;
        float w2[2];
        #pragma unroll
        for (int j = 0; j < 2; j++) w2[j] = w4[s4 + j] + t4[s4 + j];
        float t2a = __shfl_xor_sync(0xffffffffu, w2[0], 2);
        float t2b = __shfl_xor_sync(0xffffffffu, w2[1], 2);
        float w1 = (lane & 2) ? (w2[1] + t2b) : (w2[0] + t2a);
        float z = w1 + __shfl_xor_sync(0xffffffffu, w1, 1);

        // lane -> (r, bb): idx = 8*b4 + 4*b3 + 2*b2 + 1*b1
        const int idx = ((lane >> 4) & 1) * 8 + ((lane >> 3) & 1) * 4 +
                        ((lane >> 2) & 1) * 2 + ((lane >> 1) & 1);
        if (!(lane & 1))
            gsum[4 * rw + (idx >> 2)][4 * bw + (idx & 3)] = z;
        __syncthreads();

        if (tid < 32) {
            float gi = gsum[0  + ujl][ub] + xq0;
            float gf = gsum[4  + ujl][ub] + xq1;
            float gg = gsum[8  + ujl][ub] + xq2;
            float go = gsum[12 + ujl][ub] + xq3;
            float si = sigf(gi);
            float sf = sigf(gf);
            float so = sigf(go);
            float tg = tanhfast(gg);
            c_st = sf * c_st + si * tg;
            float hN = so * tanhfast(c_st);
            g_h[((size_t)(ub << 10) + t) * 512 + j0 + ujl] = hN;
            __syncwarp();
            if (lane == 0) red_rel_add(&g_ctr[t], 1u);
        }
    }
}

// ---------- generic tiled fp32 GEMM ----------
// TB==0: B is [N,K] row-major (NT). TB==1: B is [K,N] (NN). M,N %128==0, K%8==0.
// DUAL: blockIdx.z==1 switches to (dA,dB,dBias,dC,dldb) with RELU2 epilogue.
template<int TB, bool RELU, bool ACC, bool DUAL, bool RELU2>
__global__ __launch_bounds__(256) void gemm_kernel(
    const float* __restrict__ A, int lda, long long strideA,
    const float* __restrict__ B, int ldb, long long strideB,
    float* __restrict__ C, int ldc, long long strideC,
    int M, int N, int K,
    const float* __restrict__ bias, const float* __restrict__ bias2,
    const int* __restrict__ rowmask,
    const float* __restrict__ dA, const float* __restrict__ dB,
    const float* __restrict__ dBias, float* __restrict__ dC, int dldb)
{
    __shared__ __align__(16) float As[2][8][128];
    __shared__ __align__(16) float Bs[2][8][128];

    const int tid = threadIdx.x;
    const int m0 = blockIdx.y * 128;
    const int n0 = blockIdx.x * 128;
    bool relu = RELU;
    if (DUAL) {
        if (blockIdx.z == 1) { A = dA; B = dB; bias = dBias; C = dC; ldb = dldb; relu = RELU2; }
    } else {
        A += (long long)blockIdx.z * strideA;
        B += (long long)blockIdx.z * strideB;
        C += (long long)blockIdx.z * strideC;
    }

    const int ar   = tid >> 1;
    const int aseg = (tid & 1) * 4;
    const int bk   = tid >> 5;
    const int bn   = (tid & 31) * 4;
    const int nk   = K >> 3;

    {
        float4 a4 = *(const float4*)(A + (size_t)(m0 + ar) * lda + aseg);
        As[0][aseg + 0][ar] = a4.x; As[0][aseg + 1][ar] = a4.y;
        As[0][aseg + 2][ar] = a4.z; As[0][aseg + 3][ar] = a4.w;
        if (TB == 0) {
            float4 b4 = *(const float4*)(B + (size_t)(n0 + ar) * ldb + aseg);
            Bs[0][aseg + 0][ar] = b4.x; Bs[0][aseg + 1][ar] = b4.y;
            Bs[0][aseg + 2][ar] = b4.z; Bs[0][aseg + 3][ar] = b4.w;
        } else {
            *(float4*)&Bs[0][bk][bn] = *(const float4*)(B + (size_t)bk * ldb + n0 + bn);
        }
    }
    __syncthreads();

    float acc[8][8];
    #pragma unroll
    for (int i = 0; i < 8; i++)
        #pragma unroll
        for (int j = 0; j < 8; j++) acc[i][j] = 0.f;

    const int tm = (tid >> 4) << 3;
    const int tn = (tid & 15) << 3;

    for (int kt = 0; kt < nk; ++kt) {
        const int cur = kt & 1, nxt = cur ^ 1;
        float4 na, nb;
        if (kt + 1 < nk) {
            const int k0 = (kt + 1) << 3;
            na = *(const float4*)(A + (size_t)(m0 + ar) * lda + k0 + aseg);
            if (TB == 0)
                nb = *(const float4*)(B + (size_t)(n0 + ar) * ldb + k0 + aseg);
            else
                nb = *(const float4*)(B + (size_t)(k0 + bk) * ldb + n0 + bn);
        }
        #pragma unroll
        for (int kk = 0; kk < 8; ++kk) {
            float4 aa0 = *(const float4*)&As[cur][kk][tm];
            float4 aa1 = *(const float4*)&As[cur][kk][tm + 4];
            float4 bb0 = *(const float4*)&Bs[cur][kk][tn];
            float4 bb1 = *(const float4*)&Bs[cur][kk][tn + 4];
            float av_[8] = {aa0.x, aa0.y, aa0.z, aa0.w, aa1.x, aa1.y, aa1.z, aa1.w};
            float bv_[8] = {bb0.x, bb0.y, bb0.z, bb0.w, bb1.x, bb1.y, bb1.z, bb1.w};
            #pragma unroll
            for (int i = 0; i < 8; i++)
                #pragma unroll
                for (int j = 0; j < 8; j++)
                    acc[i][j] = fmaf(av_[i], bv_[j], acc[i][j]);
        }
        if (kt + 1 < nk) {
            As[nxt][aseg + 0][ar] = na.x; As[nxt][aseg + 1][ar] = na.y;
            As[nxt][aseg + 2][ar] = na.z; As[nxt][aseg + 3][ar] = na.w;
            if (TB == 0) {
                Bs[nxt][aseg + 0][ar] = nb.x; Bs[nxt][aseg + 1][ar] = nb.y;
                Bs[nxt][aseg + 2][ar] = nb.z; Bs[nxt][aseg + 3][ar] = nb.w;
            } else {
                *(float4*)&Bs[nxt][bk][bn] = nb;
            }
        }
        __syncthreads();
    }

    float bvv[8];
    #pragma unroll
    for (int j = 0; j < 8; j++) {
        float b = bias ? bias[n0 + tn + j] : 0.f;
        if (bias2) b += bias2[n0 + tn + j];
        bvv[j] = b;
    }
    #pragma unroll
    for (int i = 0; i < 8; i++) {
        const int row = m0 + tm + i;
        float keep = 1.f;
        if (rowmask) keep = rowmask[row] ? 1.f : 0.f;
        float out[8];
        #pragma unroll
        for (int j = 0; j < 8; j++) {
            float v = acc[i][j] + bvv[j];
            if (relu) v = fmaxf(v, 0.f);
            out[j] = v * keep;
        }
        float* Cp = C + (size_t)row * ldc + n0 + tn;
        if (ACC) {
            float4 o0 = *(const float4*)Cp;
            float4 o1 = *(const float4*)(Cp + 4);
            out[0] += o0.x; out[1] += o0.y; out[2] += o0.z; out[3] += o0.w;
            out[4] += o1.x; out[5] += o1.y; out[6] += o1.z; out[7] += o1.w;
        }
        *(float4*)Cp       = make_float4(out[0], out[1], out[2], out[3]);
        *(float4*)(Cp + 4) = make_float4(out[4], out[5], out[6], out[7]);
    }
}

// ---------- masked softmax per row (in place) + has-neighbor flag ----------
__global__ __launch_bounds__(256) void softmax_kernel(
    float* __restrict__ S, const int* __restrict__ adj, int* __restrict__ hasnb)
{
    __shared__ float sred[32];
    const int r = blockIdx.x;
    const int i = r & 1023;
    const int tid = threadIdx.x;
    float* Sr = S + (size_t)r * 1024;
    const int* Ar = adj + (size_t)r * 1024;

    float v[4]; int ok[4];
    float mx = -3.0e38f;
    #pragma unroll
    for (int q = 0; q < 4; q++) {
        int j = tid + 256 * q;
        ok[q] = (Ar[j] > 0) && (j != i);
        v[q] = Sr[j];
        if (ok[q]) mx = fmaxf(mx, v[q]);
    }
    #pragma unroll
    for (int off = 16; off > 0; off >>= 1)
        mx = fmaxf(mx, __shfl_xor_sync(0xffffffffu, mx, off));
    if ((tid & 31) == 0) sred[tid >> 5] = mx;
    __syncthreads();
    if (tid < 32) {
        float m2 = (tid < 8) ? sred[tid] : -3.0e38f;
        #pragma unroll
        for (int off = 4; off > 0; off >>= 1)
            m2 = fmaxf(m2, __shfl_xor_sync(0xffffffffu, m2, off));
        if (tid == 0) sred[0] = m2;
    }
    __syncthreads();
    const float rowmax = sred[0];
    const bool any = rowmax > -1.0e37f;

    float e[4];
    float s = 0.f;
    #pragma unroll
    for (int q = 0; q < 4; q++) {
        e[q] = ok[q] ? __expf(v[q] - rowmax) : 0.f;
        s += e[q];
    }
    #pragma unroll
    for (int off = 16; off > 0; off >>= 1)
        s += __shfl_xor_sync(0xffffffffu, s, off);
    __syncthreads();
    if ((tid & 31) == 0) sred[tid >> 5] = s;
    __syncthreads();
    if (tid < 32) {
        float s2 = (tid < 8) ? sred[tid] : 0.f;
        #pragma unroll
        for (int off = 4; off > 0; off >>= 1)
            s2 += __shfl_xor_sync(0xffffffffu, s2, off);
        if (tid == 0) sred[0] = s2;
    }
    __syncthreads();
    const float inv = any ? (1.f / sred[0]) : 0.f;
    #pragma unroll
    for (int q = 0; q < 4; q++)
        Sr[tid + 256 * q] = e[q] * inv;
    if (tid == 0) hasnb[r] = any ? 1 : 0;
}

extern "C" void kernel_launch(void* const* d_in, const int* in_sizes, int n_in,
                              void* d_out, int out_size)
{
    const float* feats  = (const float*)d_in[0];
    const int*   adj    = (const int*)  d_in[1];
    const float* W_ih   = (const float*)d_in[2];
    const float* W_hh   = (const float*)d_in[3];
    const float* b_ih   = (const float*)d_in[4];
    const float* b_hh   = (const float*)d_in[5];
    const float* gx_W1  = (const float*)d_in[6];
    const float* gx_b1  = (const float*)d_in[7];
    const float* gx_W2  = (const float*)d_in[8];
    const float* gx_b2  = (const float*)d_in[9];
    const float* gz_W1  = (const float*)d_in[10];
    const float* gz_b1  = (const float*)d_in[11];
    const float* gz_W2  = (const float*)d_in[12];
    const float* gz_b2  = (const float*)d_in[13];
    const float* gv_W1  = (const float*)d_in[14];
    const float* gv_b1  = (const float*)d_in[15];
    const float* gv_W2  = (const float*)d_in[16];
    const float* gv_b2  = (const float*)d_in[17];
    const float* gn_W1  = (const float*)d_in[18];
    const float* gn_b1  = (const float*)d_in[19];
    const float* gn_W2  = (const float*)d_in[20];
    const float* gn_b2  = (const float*)d_in[21];
    const float* out_W  = (const float*)d_in[22];
    const float* out_b  = (const float*)d_in[23];
    float* out = (float*)d_out;

    float *xproj, *h, *t1, *t2, *t3, *ax, *av, *scores, *sagg, *agg;
    int* hasnb;
    cudaGetSymbolAddress((void**)&xproj,  g_xproj);
    cudaGetSymbolAddress((void**)&h,      g_h);
    cudaGetSymbolAddress((void**)&t1,     g_t1);
    cudaGetSymbolAddress((void**)&t2,     g_t2);
    cudaGetSymbolAddress((void**)&t3,     g_t3);
    cudaGetSymbolAddress((void**)&ax,     g_ax);
    cudaGetSymbolAddress((void**)&av,     g_av);
    cudaGetSymbolAddress((void**)&scores, g_scores);
    cudaGetSymbolAddress((void**)&sagg,   g_sagg);
    cudaGetSymbolAddress((void**)&agg,    g_agg);
    cudaGetSymbolAddress((void**)&hasnb,  g_hasnb);

    reset_kernel<<<1, 1024>>>();

    // x_proj = feats @ W_ih^T + (b_ih + b_hh) : [8192,2048], K=256
    gemm_kernel<0, false, false, false, false><<<dim3(16, 64, 1), 256>>>(
        feats, 256, 0, W_ih, 256, 0, xproj, 2048, 0,
        8192, 2048, 256, b_ih, b_hh, nullptr,
        nullptr, nullptr, nullptr, nullptr, 0);

    lstm_kernel<<<128, 256>>>(W_hh);

    // ax/av MLP layer 1 (paired): h@gx_W1^T->t1 ; h@gv_W1^T->t3
    gemm_kernel<0, true , false, true, true><<<dim3(2, 64, 2), 256>>>(
        h, 512, 0, gx_W1, 512, 0, t1, 256, 0, 8192, 256, 512, gx_b1, nullptr, nullptr,
        h, gv_W1, gv_b1, t3, 512);
    // ax/av MLP layer 2 (paired): t1@gx_W2^T->ax ; t3@gv_W2^T->av
    gemm_kernel<0, false, false, true, false><<<dim3(2, 64, 2), 256>>>(
        t1, 256, 0, gx_W2, 256, 0, ax, 256, 0, 8192, 256, 256, gx_b2, nullptr, nullptr,
        t3, gv_W2, gv_b2, av, 256);

    // scores[b] = ax[b] @ av[b]^T
    gemm_kernel<0, false, false, false, false><<<dim3(8, 8, 8), 256>>>(
        ax, 256, 1024LL * 256, av, 256, 1024LL * 256,
        scores, 1024, 1024LL * 1024, 1024, 1024, 256, nullptr, nullptr, nullptr,
        nullptr, nullptr, nullptr, nullptr, 0);

    softmax_kernel<<<8192, 256>>>(scores, adj, hasnb);

    // sagg[b] = w[b] @ h[b]
    gemm_kernel<1, false, false, false, false><<<dim3(4, 8, 8), 256>>>(
        scores, 1024, 1024LL * 1024, h, 512, 1024LL * 512,
        sagg, 512, 1024LL * 512, 1024, 512, 1024, nullptr, nullptr, nullptr,
        nullptr, nullptr, nullptr, nullptr, 0);

    // paired: out_part = h @ out_W[:, :512]^T + out_b  ;  t1 = relu(sagg@gz_W1^T + gz_b1)
    gemm_kernel<0, false, false, true, true><<<dim3(2, 64, 2), 256>>>(
        h, 512, 0, out_W, 768, 0, out, 256, 0, 8192, 256, 512, out_b, nullptr, nullptr,
        sagg, gz_W1, gz_b1, t1, 512);

    // agg = MLP_gn(MLP_gz(...)) with isolated-node zeroing
    gemm_kernel<0, false, false, false, false><<<dim3(2, 64, 1), 256>>>(
        t1, 256, 0, gz_W2, 256, 0, t2, 256, 0, 8192, 256, 256, gz_b2, nullptr, nullptr,
        nullptr, nullptr, nullptr, nullptr, 0);
    gemm_kernel<0, true , false, false, false><<<dim3(2, 64, 1), 256>>>(
        t2, 256, 0, gn_W1, 256, 0, t1, 256, 0, 8192, 256, 256, gn_b1, nullptr, nullptr,
        nullptr, nullptr, nullptr, nullptr, 0);
    gemm_kernel<0, false, false, false, false><<<dim3(2, 64, 1), 256>>>(
        t1, 256, 0, gn_W2, 256, 0, agg, 256, 0, 8192, 256, 256, gn_b2, nullptr, hasnb,
        nullptr, nullptr, nullptr, nullptr, 0);

    // out += agg @ out_W[:, 512:]^T
    gemm_kernel<0, false, true , false, false><<<dim3(2, 64, 1), 256>>>(
        agg, 256, 0, out_W + 512, 768, 0, out, 256, 0, 8192, 256, 256, nullptr, nullptr, nullptr,
        nullptr, nullptr, nullptr, nullptr, 0);
}